// round 2
// baseline (speedup 1.0000x reference)
#include <cuda_runtime.h>

// Problem constants: N=1, C=64, H=W=80
#define LL    6400      // H*W
#define WW    80
#define NTILE 50        // 6400 / 128
#define NEGV  (-1e9f)

// Scratch (static __device__ — no allocations allowed)
__device__ float g_rowv[LL * NTILE];   // per-(row, coltile) partial max
__device__ int   g_rowj[LL * NTILE];   // per-(row, coltile) partial argmax (first occurrence)
__device__ float g_colp[LL * NTILE];   // per-(col, rowtile) partial max
__device__ float g_colmax[LL];         // final column max

// Packed fp32x2 FMA (Blackwell): d = a*b + d per 32-bit lane of the 64-bit regs.
// IEEE-identical to two scalar fmaf, so all downstream equality logic is unchanged.
__device__ __forceinline__ void ffma2(unsigned long long& d,
                                      unsigned long long a,
                                      unsigned long long b)
{
    asm("fma.rn.f32x2 %0, %1, %2, %0;" : "+l"(d) : "l"(a), "l"(b));
}

// Broadcast one fp32 into both halves of a 64-bit packed register.
__device__ __forceinline__ unsigned long long bcast2(float v)
{
    unsigned long long r;
    asm("mov.b64 %0, {%1, %1};" : "=l"(r) : "r"(__float_as_uint(v)));
    return r;
}

// ---------------------------------------------------------------------------
// Kernel 1: fused conf tile + reductions.
// conf[i,j] = dot_c(A[c,i], B[c,j]) * 0.15625  (== /(sqrt(64)^2 * 0.1)),
// masked to NEGV where saliency invalid. Each (i,j) computed exactly once,
// reduced into row-(max,argmax) and col-max partials. conf never stored.
// Mainloop uses packed fma.rn.f32x2: acc2[x2][y] holds rows (2*x2, 2*x2+1).
// ---------------------------------------------------------------------------
__global__ __launch_bounds__(256, 2)
void conf_kernel(const float* __restrict__ A, const float* __restrict__ B,
                 const float* __restrict__ saV, const float* __restrict__ saI)
{
    __shared__ float As[32][128];
    __shared__ float Bs[32][128];
    __shared__ float colsm[16][128];

    const int ct = blockIdx.x;          // column tile
    const int rt = blockIdx.y;          // row tile
    const int i0 = rt * 128;
    const int j0 = ct * 128;
    const int tid = threadIdx.x;
    const int tx = tid >> 4;            // 0..15 -> 8 rows each
    const int ty = tid & 15;            // 0..15 -> 8 cols each

    unsigned long long acc2[4][8];      // [x-pair][y]; low half = even row
#pragma unroll
    for (int x2 = 0; x2 < 4; x2++)
#pragma unroll
        for (int y = 0; y < 8; y++) acc2[x2][y] = 0ull;

    // K=64 in two 32-deep phases (keeps static smem at 40KB)
    for (int kb = 0; kb < 64; kb += 32) {
#pragma unroll
        for (int s = 0; s < 4; s++) {
            int f4 = tid + s * 256;          // 1024 float4 per tile
            int c  = f4 >> 5;                // 0..31
            int i4 = (f4 & 31) << 2;         // 0..124 step 4
            *(float4*)&As[c][i4] = *(const float4*)&A[(kb + c) * LL + i0 + i4];
            *(float4*)&Bs[c][i4] = *(const float4*)&B[(kb + c) * LL + j0 + i4];
        }
        __syncthreads();

#pragma unroll 8
        for (int k = 0; k < 32; k++) {
            // a-pairs: free bit-cast of the float4 smem loads
            __align__(16) unsigned long long a2[4];
            *(float4*)&a2[0] = *(float4*)&As[k][tx * 8];
            *(float4*)&a2[2] = *(float4*)&As[k][tx * 8 + 4];
            float b[8];
            *(float4*)&b[0] = *(float4*)&Bs[k][ty * 8];
            *(float4*)&b[4] = *(float4*)&Bs[k][ty * 8 + 4];
#pragma unroll
            for (int y = 0; y < 8; y++) {
                unsigned long long bb = bcast2(b[y]);
#pragma unroll
                for (int x2 = 0; x2 < 4; x2++)
                    ffma2(acc2[x2][y], a2[x2], bb);
            }
        }
        __syncthreads();
    }

    // Unpack packed accumulators -> acc[x][y] (low half is even row)
    float acc[8][8];
#pragma unroll
    for (int x2 = 0; x2 < 4; x2++)
#pragma unroll
        for (int y = 0; y < 8; y++) {
            float2 f = *(float2*)&acc2[x2][y];
            acc[2 * x2][y]     = f.x;
            acc[2 * x2 + 1][y] = f.y;
        }

    // Saliency validity masks
    bool vr[8], vc[8];
#pragma unroll
    for (int x = 0; x < 8; x++) vr[x] = saV[i0 + tx * 8 + x] > 0.f;
#pragma unroll
    for (int y = 0; y < 8; y++) vc[y] = saI[j0 + ty * 8 + y] > 0.f;

    // Scale + mask in place (this is THE conf value; used for both reductions)
#pragma unroll
    for (int x = 0; x < 8; x++)
#pragma unroll
        for (int y = 0; y < 8; y++)
            acc[x][y] = (vr[x] && vc[y]) ? acc[x][y] * 0.15625f : NEGV;

    // -------- column partial max (over this thread's 8 rows) --------
#pragma unroll
    for (int y = 0; y < 8; y++) {
        float m = acc[0][y];
#pragma unroll
        for (int x = 1; x < 8; x++) m = fmaxf(m, acc[x][y]);
        colsm[tx][ty * 8 + y] = m;
    }

    // -------- row (max, first-argmax): local scan + shfl over 16 lanes --------
#pragma unroll
    for (int x = 0; x < 8; x++) {
        float v = acc[x][0];
        int   j = j0 + ty * 8;
#pragma unroll
        for (int y = 1; y < 8; y++) {
            if (acc[x][y] > v) { v = acc[x][y]; j = j0 + ty * 8 + y; }
        }
        // reduce across the 16 ty-lanes (lanes [0..15] and [16..31] are
        // independent 16-groups since lane = (tx&1)*16 + ty). ties -> min j.
#pragma unroll
        for (int d = 1; d < 16; d <<= 1) {
            float ov = __shfl_xor_sync(0xffffffffu, v, d);
            int   oj = __shfl_xor_sync(0xffffffffu, j, d);
            if (ov > v || (ov == v && oj < j)) { v = ov; j = oj; }
        }
        if (ty == 0) {
            int i = i0 + tx * 8 + x;
            g_rowv[i * NTILE + ct] = v;
            g_rowj[i * NTILE + ct] = j;
        }
    }

    __syncthreads();
    // finish column reduction across the 16 tx-groups
    if (tid < 128) {
        float m = colsm[0][tid];
#pragma unroll
        for (int t = 1; t < 16; t++) m = fmaxf(m, colsm[t][tid]);
        g_colp[(j0 + tid) * NTILE + rt] = m;
    }
}

// ---------------------------------------------------------------------------
// Kernel 2: reduce column partials -> g_colmax
// ---------------------------------------------------------------------------
__global__ void colmax_kernel()
{
    int j = blockIdx.x * 256 + threadIdx.x;
    if (j >= LL) return;
    float m = g_colp[j * NTILE];
#pragma unroll 5
    for (int t = 1; t < NTILE; t++) m = fmaxf(m, g_colp[j * NTILE + t]);
    g_colmax[j] = m;
}

// ---------------------------------------------------------------------------
// Kernel 3: per-row finalize — mutual-NN test + outputs
// out layout (flattened tuple, float32):
//   [0      : 12800)  mkpts0  [L,2]
//   [12800  : 25600)  mkpts1  [1,L,2]
//   [25600  : 32000)  mask_v  [1,L]
//   [32000  : 38400)  score   [1,L]
//   [38400  : 448000) sa_ir_up [1,1,640,640]
// ---------------------------------------------------------------------------
__global__ void finalize_kernel(float* __restrict__ out)
{
    int i = blockIdx.x * 256 + threadIdx.x;
    if (i >= LL) return;

    float best = g_rowv[i * NTILE];
    int   bj   = g_rowj[i * NTILE];
#pragma unroll 5
    for (int t = 1; t < NTILE; t++) {
        float v = g_rowv[i * NTILE + t];
        if (v > best) { best = v; bj = g_rowj[i * NTILE + t]; }  // strict > keeps first occurrence
    }

    // mutual nearest neighbor: row max must also be its column's max, and > 0
    float mv = (best > 0.f && best == g_colmax[bj]) ? 1.f : 0.f;
    int   aj = (mv > 0.f) ? bj : 0;   // jnp.argmax of all-zero mask row -> 0

    out[2 * i]     = (float)((i % WW) * 8);
    out[2 * i + 1] = (float)((i / WW) * 8);
    out[12800 + 2 * i]     = (float)((aj % WW) * 8);
    out[12800 + 2 * i + 1] = (float)((aj / WW) * 8);
    out[25600 + i] = mv;
    out[32000 + i] = (mv > 0.f) ? best : 0.f;
}

// ---------------------------------------------------------------------------
// Kernel 4: bilinear upsample 80x80 -> 640x640, align_corners=True
// ---------------------------------------------------------------------------
__global__ void upsample_kernel(const float* __restrict__ in, float* __restrict__ out)
{
    int o = blockIdx.x * 256 + threadIdx.x;
    if (o >= 640 * 640) return;
    int oy = o / 640, ox = o % 640;
    const float step = 79.0f / 639.0f;
    float ysf = oy * step;
    float xsf = ox * step;
    int y0 = (int)ysf;                 // ysf >= 0 -> trunc == floor
    int x0 = (int)xsf;
    int y1 = min(y0 + 1, WW - 1);
    int x1 = min(x0 + 1, WW - 1);
    float wy = ysf - (float)y0;
    float wx = xsf - (float)x0;
    float v00 = in[y0 * WW + x0], v01 = in[y0 * WW + x1];
    float v10 = in[y1 * WW + x0], v11 = in[y1 * WW + x1];
    float r0 = v00 * (1.f - wy) + v10 * wy;   // interp along H first (matches reference)
    float r1 = v01 * (1.f - wy) + v11 * wy;
    out[38400 + o] = r0 * (1.f - wx) + r1 * wx;
}

// ---------------------------------------------------------------------------
extern "C" void kernel_launch(void* const* d_in, const int* in_sizes, int n_in,
                              void* d_out, int out_size)
{
    const float* A   = (const float*)d_in[0];   // feat_reg_vi [1,64,80,80]
    const float* B   = (const float*)d_in[1];   // feat_reg_ir [1,64,80,80]
    const float* saV = (const float*)d_in[2];   // feat_sa_vi  [1,1,80,80]
    const float* saI = (const float*)d_in[3];   // feat_sa_ir  [1,1,80,80]
    float* out = (float*)d_out;

    dim3 grid(NTILE, NTILE);
    conf_kernel<<<grid, 256>>>(A, B, saV, saI);
    colmax_kernel<<<25, 256>>>();
    finalize_kernel<<<25, 256>>>(out);
    upsample_kernel<<<1600, 256>>>(saI, out);
}